// round 15
// baseline (speedup 1.0000x reference)
#include <cuda_runtime.h>

#define Bn 256
#define Sn 336
#define Cn 321
#define Hn 512
#define Pn 96
#define NCTA 88
#define AROW 514   // As rows (512 + 2 prefetch pad)
#define BROW 514   // Bs rows (512 + 2 prefetch pad)

typedef unsigned long long ull;

__device__ float g_scr[(size_t)Bn * Cn * Hn];

__device__ __forceinline__ void fma2(ull &d, ull a, ull b) {
    asm("fma.rn.f32x2 %0, %1, %2, %0;" : "+l"(d) : "l"(a), "l"(b));
}
__device__ __forceinline__ ull dup2(float v) {
    ull r; asm("mov.b64 %0, {%1, %1};" : "=l"(r) : "f"(v)); return r;
}
__device__ __forceinline__ float2 up2(ull v) {
    float2 r; asm("mov.b64 {%0, %1}, %2;" : "=f"(r.x), "=f"(r.y) : "l"(v)); return r;
}
__device__ __forceinline__ float reluN(float x) { return (x < 0.f) ? 0.f : x; }
__device__ __forceinline__ void cluster_sync() {
    asm volatile("barrier.cluster.arrive.aligned;" ::: "memory");
    asm volatile("barrier.cluster.wait.aligned;" ::: "memory");
}

// ============================================================================
// it_kernel: IT[b,c,h] = bi[h] + sum_s x[b,s,c]*Wi[h,s]   (round-7, proven)
// ============================================================================
__global__ void __launch_bounds__(128) it_kernel(
    const float* __restrict__ x, const float* __restrict__ Wi,
    const float* __restrict__ bi)
{
    __shared__ __align__(16) float As[16][68];
    __shared__ __align__(16) float Bs[16][68];
    const int b  = blockIdx.z;
    const int n0 = blockIdx.x * 64;
    const int m0 = blockIdx.y * 64;
    const int t  = threadIdx.x;
    const int tm = t & 15, tn = t >> 4;

    ull acc[4][4];
#pragma unroll
    for (int i = 0; i < 4; i++)
#pragma unroll
        for (int j = 0; j < 4; j++) acc[i][j] = 0ull;

    const float* xb = x + (size_t)b * Sn * Cn;
    const int la_k = t >> 3, la_c = (t & 7) * 8;
    const int lb_n = t & 63, lb_k = (t >> 6) * 8;

    for (int k0 = 0; k0 < Sn; k0 += 16) {
        {
            const float* src = xb + (size_t)(k0 + la_k) * Cn + m0 + la_c;
#pragma unroll
            for (int j = 0; j < 8; j++)
                As[la_k][la_c + j] = (m0 + la_c + j < Cn) ? src[j] : 0.f;
        }
        {
            const float* src = Wi + (size_t)(n0 + lb_n) * Sn + k0 + lb_k;
            float4 v0 = *(const float4*)(src);
            float4 v1 = *(const float4*)(src + 4);
            Bs[lb_k + 0][lb_n] = v0.x; Bs[lb_k + 1][lb_n] = v0.y;
            Bs[lb_k + 2][lb_n] = v0.z; Bs[lb_k + 3][lb_n] = v0.w;
            Bs[lb_k + 4][lb_n] = v1.x; Bs[lb_k + 5][lb_n] = v1.y;
            Bs[lb_k + 6][lb_n] = v1.z; Bs[lb_k + 7][lb_n] = v1.w;
        }
        __syncthreads();
#pragma unroll
        for (int kk = 0; kk < 16; kk++) {
            float4 a = *(const float4*)&As[kk][tm * 4];
            const ull* bp = (const ull*)&Bs[kk][tn * 8];
            ull b0 = bp[0], b1 = bp[1], b2 = bp[2], b3 = bp[3];
            ull a0 = dup2(a.x), a1 = dup2(a.y), a2 = dup2(a.z), a3 = dup2(a.w);
            fma2(acc[0][0], a0, b0); fma2(acc[0][1], a0, b1);
            fma2(acc[0][2], a0, b2); fma2(acc[0][3], a0, b3);
            fma2(acc[1][0], a1, b0); fma2(acc[1][1], a1, b1);
            fma2(acc[1][2], a1, b2); fma2(acc[1][3], a1, b3);
            fma2(acc[2][0], a2, b0); fma2(acc[2][1], a2, b1);
            fma2(acc[2][2], a2, b2); fma2(acc[2][3], a2, b3);
            fma2(acc[3][0], a3, b0); fma2(acc[3][1], a3, b1);
            fma2(acc[3][2], a3, b2); fma2(acc[3][3], a3, b3);
        }
        __syncthreads();
    }
    float biv[8];
#pragma unroll
    for (int j = 0; j < 8; j++) biv[j] = bi[n0 + tn * 8 + j];
#pragma unroll
    for (int i = 0; i < 4; i++) {
        int c = m0 + tm * 4 + i;
        if (c < Cn) {
            float* dst = g_scr + ((size_t)b * Cn + c) * Hn + n0 + tn * 8;
#pragma unroll
            for (int j = 0; j < 4; j++) {
                float2 v = up2(acc[i][j]);
                dst[2 * j]     = v.x + biv[2 * j];
                dst[2 * j + 1] = v.y + biv[2 * j + 1];
            }
        }
    }
}

// ============================================================================
// Persistent recurrence (single launch, all 255 steps): 11 clusters x 8 CTAs,
// 256 threads.
//   Staging: ALL 8 warps stage the full 512-k A tile (warp w owns k-window
//     [w*64, w*64+64)) -- halves the serialized staging phase vs 4 warps.
//   Compute: warps 0-3, single uninterrupted 512-kk distance-2 register
//     pipeline; fma2 order = k ascending 0..511 -> bit-identical trajectory.
// Per step: 1 __syncthreads (post-stage) + 1 cluster_sync (post-epilogue).
// smem: Bs[514][64] + As[514][36] = 205.6KB, 1 CTA/SM.
// ============================================================================
extern __shared__ float sm_dyn[];

__global__ void __cluster_dims__(8, 1, 1) __launch_bounds__(256, 1) rnn_kernel(
    const float* __restrict__ Wh, const float* __restrict__ bh)
{
    float* Bs = sm_dyn;                     // Bs[k*64 + n], k < BROW
    float* As = sm_dyn + BROW * 64;         // As[kk*36 + c], kk < AROW

    const int t   = threadIdx.x;
    const int cta = blockIdx.x;
    const int n0  = (cta & 7) * 64;
    const int m0  = (cta >> 3) * 32;
    const bool consumer = (t < 128);
    const int tm  = t & 7;
    const int tn  = (t & 127) >> 3;

    // Wh^T resident: Bs[k][n] = Wh[n0+n][k]  (all 256 threads, 128 k each)
    {
        const int n = t & 63, kb = (t >> 6) * 128;
        const float* src = Wh + (size_t)(n0 + n) * Hn + kb;
        for (int k = 0; k < 128; k += 4) {
            float4 v = *(const float4*)(src + k);
            Bs[(kb + k + 0) * 64 + n] = v.x; Bs[(kb + k + 1) * 64 + n] = v.y;
            Bs[(kb + k + 2) * 64 + n] = v.z; Bs[(kb + k + 3) * 64 + n] = v.w;
        }
    }
    float bhv[4];
#pragma unroll
    for (int j = 0; j < 4; j++) bhv[j] = bh[n0 + tn * 4 + j];
    __syncthreads();

    // step 0: h0 = reluN(reluN(it+bh)+bh) on own tile (consumers)
    if (consumer) {
#pragma unroll
        for (int i = 0; i < 4; i++) {
            int c = m0 + tm * 4 + i;
            if (c < Cn) {
                float* row = g_scr + (size_t)c * Hn + n0 + tn * 4;
                float4 v = *(const float4*)row;
                float f[4] = { v.x, v.y, v.z, v.w };
#pragma unroll
                for (int j = 0; j < 4; j++) {
                    float a = reluN(f[j] + bhv[j]);
                    f[j] = reluN(a + bhv[j]);
                }
                *(float4*)row = make_float4(f[0], f[1], f[2], f[3]);
            }
        }
    }
    cluster_sync();

    // staging lane mapping: ALL threads. lane la_c owns c-row m0+la_c;
    // warp w (0..7) owns k-window [w*64, w*64+64) -> 2 ping-pong batches.
    const int la_c  = t & 31;
    const int la_kw = (t >> 5) * 64;
    const bool cv   = (m0 + la_c) < Cn;

    for (int b = 1; b < Bn; b++) {
        float* itrow = g_scr + (size_t)b * (Cn * Hn);

        ull acc[4][2];
        float4 itv[4];

        if (consumer) {
#pragma unroll
            for (int i = 0; i < 4; i++) { acc[i][0] = 0ull; acc[i][1] = 0ull; }
#pragma unroll
            for (int i = 0; i < 4; i++) {
                int c = m0 + tm * 4 + i;
                itv[i] = (c < Cn)
                    ? *(const float4*)(itrow + (size_t)c * Hn + n0 + tn * 4)
                    : make_float4(0.f, 0.f, 0.f, 0.f);
            }
        }

        // stage this thread's 64-k window of the A tile (2 batches of 8 f4)
        {
            const float* arow = g_scr + (size_t)(b - 1) * (Cn * Hn)
                              + (size_t)(m0 + la_c) * Hn + la_kw;
            float4 pA[8], pB[8];
#pragma unroll
            for (int q = 0; q < 8; q++)
                pA[q] = cv ? *(const float4*)(arow + q * 4)
                           : make_float4(0.f, 0.f, 0.f, 0.f);
#pragma unroll
            for (int q = 0; q < 8; q++)
                pB[q] = cv ? *(const float4*)(arow + 32 + q * 4)
                           : make_float4(0.f, 0.f, 0.f, 0.f);
            float* d = As;
#pragma unroll
            for (int q = 0; q < 8; q++) {
                int kr = la_kw + q * 4;
                d[(kr + 0) * 36 + la_c] = pA[q].x;
                d[(kr + 1) * 36 + la_c] = pA[q].y;
                d[(kr + 2) * 36 + la_c] = pA[q].z;
                d[(kr + 3) * 36 + la_c] = pA[q].w;
            }
#pragma unroll
            for (int q = 0; q < 8; q++) {
                int kr = la_kw + 32 + q * 4;
                d[(kr + 0) * 36 + la_c] = pB[q].x;
                d[(kr + 1) * 36 + la_c] = pB[q].y;
                d[(kr + 2) * 36 + la_c] = pB[q].z;
                d[(kr + 3) * 36 + la_c] = pB[q].w;
            }
        }
        __syncthreads();   // A tile fully staged

        if (consumer) {
            const float* as = As + tm * 4;
            const float* bs = Bs + tn * 4;

            // one uninterrupted 512-kk distance-2 register pipeline;
            // tail prefetches hit pad rows (never used in arithmetic).
            float4 aC = *(const float4*)(as);
            float4 aN = *(const float4*)(as + 36);
            ulonglong2 bC = *(const ulonglong2*)(bs);
            ulonglong2 bN = *(const ulonglong2*)(bs + 64);
#pragma unroll 1
            for (int kt = 0; kt < 32; kt++) {
                const float* asv = as + (kt * 16 + 2) * 36;
                const float* bsv = bs + (kt * 16 + 2) * 64;
#pragma unroll
                for (int kk = 0; kk < 16; kk++) {
                    float4 aP = *(const float4*)(asv + kk * 36);
                    ulonglong2 bP = *(const ulonglong2*)(bsv + kk * 64);
                    ull a0 = dup2(aC.x), a1 = dup2(aC.y),
                        a2 = dup2(aC.z), a3 = dup2(aC.w);
                    fma2(acc[0][0], a0, bC.x); fma2(acc[0][1], a0, bC.y);
                    fma2(acc[1][0], a1, bC.x); fma2(acc[1][1], a1, bC.y);
                    fma2(acc[2][0], a2, bC.x); fma2(acc[2][1], a2, bC.y);
                    fma2(acc[3][0], a3, bC.x); fma2(acc[3][1], a3, bC.y);
                    aC = aN; aN = aP;
                    bC = bN; bN = bP;
                }
            }

            // epilogue: h_b = reluN(reluN(it+hh)+hh), in place on g_scr[b]
#pragma unroll
            for (int i = 0; i < 4; i++) {
                int c = m0 + tm * 4 + i;
                if (c < Cn) {
                    float* row = itrow + (size_t)c * Hn + n0 + tn * 4;
                    float it[4] = { itv[i].x, itv[i].y, itv[i].z, itv[i].w };
                    float2 v0 = up2(acc[i][0]);
                    float2 v1 = up2(acc[i][1]);
                    float hh[4] = { v0.x + bhv[0], v0.y + bhv[1],
                                    v1.x + bhv[2], v1.y + bhv[3] };
                    float f[4];
#pragma unroll
                    for (int j = 0; j < 4; j++) {
                        float a = reluN(it[j] + hh[j]);
                        f[j] = reluN(a + hh[j]);
                    }
                    *(float4*)row = make_float4(f[0], f[1], f[2], f[3]);
                }
            }
        }
        // release next step's staging only after all epilogues in cluster;
        // also prevents overwriting As while consumers still read it.
        if (b < Bn - 1) cluster_sync();
    }
}

// ============================================================================
// final_kernel: tile 64c x 96p, micro 4c x 8p  (round-7, proven)
// ============================================================================
__global__ void __launch_bounds__(192) final_kernel(
    const float* __restrict__ Wf, const float* __restrict__ bf,
    float* __restrict__ out)
{
    __shared__ __align__(16) float As[16][68];
    __shared__ __align__(16) float Bs[16][100];
    const int b  = blockIdx.y;
    const int m0 = blockIdx.x * 64;
    const int t  = threadIdx.x;
    const int tm = t & 15;
    const int tn = t >> 4;

    ull acc[4][4];
#pragma unroll
    for (int i = 0; i < 4; i++)
#pragma unroll
        for (int j = 0; j < 4; j++) acc[i][j] = 0ull;

    const float* hb = g_scr + (size_t)b * Cn * Hn;
    const int la_c = t >> 1, la_k = (t & 1) * 8;
    const int lb_p = t % 96,  lb_k = (t / 96) * 8;

    for (int k0 = 0; k0 < Hn; k0 += 16) {
        if (t < 128) {
            int c = m0 + la_c;
            if (c < Cn) {
                const float* src = hb + (size_t)c * Hn + k0 + la_k;
                float4 v0 = *(const float4*)(src);
                float4 v1 = *(const float4*)(src + 4);
                As[la_k + 0][la_c] = v0.x; As[la_k + 1][la_c] = v0.y;
                As[la_k + 2][la_c] = v0.z; As[la_k + 3][la_c] = v0.w;
                As[la_k + 4][la_c] = v1.x; As[la_k + 5][la_c] = v1.y;
                As[la_k + 6][la_c] = v1.z; As[la_k + 7][la_c] = v1.w;
            } else {
#pragma unroll
                for (int j = 0; j < 8; j++) As[la_k + j][la_c] = 0.f;
            }
        }
        {
            const float* src = Wf + (size_t)lb_p * Hn + k0 + lb_k;
            float4 v0 = *(const float4*)(src);
            float4 v1 = *(const float4*)(src + 4);
            Bs[lb_k + 0][lb_p] = v0.x; Bs[lb_k + 1][lb_p] = v0.y;
            Bs[lb_k + 2][lb_p] = v0.z; Bs[lb_k + 3][lb_p] = v0.w;
            Bs[lb_k + 4][lb_p] = v1.x; Bs[lb_k + 5][lb_p] = v1.y;
            Bs[lb_k + 6][lb_p] = v1.z; Bs[lb_k + 7][lb_p] = v1.w;
        }
        __syncthreads();
#pragma unroll
        for (int kk = 0; kk < 16; kk++) {
            float4 a = *(const float4*)&As[kk][tm * 4];
            ulonglong2 b01 = *(const ulonglong2*)&Bs[kk][tn * 8];
            ulonglong2 b23 = *(const ulonglong2*)&Bs[kk][tn * 8 + 4];
            ull a0 = dup2(a.x), a1 = dup2(a.y), a2 = dup2(a.z), a3 = dup2(a.w);
            fma2(acc[0][0], a0, b01.x); fma2(acc[0][1], a0, b01.y);
            fma2(acc[0][2], a0, b23.x); fma2(acc[0][3], a0, b23.y);
            fma2(acc[1][0], a1, b01.x); fma2(acc[1][1], a1, b01.y);
            fma2(acc[1][2], a1, b23.x); fma2(acc[1][3], a1, b23.y);
            fma2(acc[2][0], a2, b01.x); fma2(acc[2][1], a2, b01.y);
            fma2(acc[2][2], a2, b23.x); fma2(acc[2][3], a2, b23.y);
            fma2(acc[3][0], a3, b01.x); fma2(acc[3][1], a3, b01.y);
            fma2(acc[3][2], a3, b23.x); fma2(acc[3][3], a3, b23.y);
        }
        __syncthreads();
    }
    float bfv[8];
#pragma unroll
    for (int j = 0; j < 8; j++) bfv[j] = bf[tn * 8 + j];
#pragma unroll
    for (int i = 0; i < 4; i++) {
        int c = m0 + tm * 4 + i;
        if (c < Cn) {
            size_t base = ((size_t)b * Pn + tn * 8) * Cn + c;
#pragma unroll
            for (int j = 0; j < 4; j++) {
                float2 v = up2(acc[i][j]);
                float z0 = v.x + bfv[2 * j];
                float z1 = v.y + bfv[2 * j + 1];
                out[base + (size_t)(2 * j) * Cn]     = (z0 >= 0.f) ? 1.f : 0.f;
                out[base + (size_t)(2 * j + 1) * Cn] = (z1 >= 0.f) ? 1.f : 0.f;
            }
        }
    }
}

// ============================================================================
extern "C" void kernel_launch(void* const* d_in, const int* in_sizes, int n_in,
                              void* d_out, int out_size) {
    const float* x  = (const float*)d_in[0];
    const float* Wi = (const float*)d_in[1];
    const float* bi = (const float*)d_in[2];
    const float* Wh = (const float*)d_in[3];
    const float* bh = (const float*)d_in[4];
    const float* Wf = (const float*)d_in[5];
    const float* bf = (const float*)d_in[6];
    float* out = (float*)d_out;

    const int smem = (BROW * 64 + AROW * 36) * 4;  // 205600 B
    cudaFuncSetAttribute(rnn_kernel,
                         cudaFuncAttributeMaxDynamicSharedMemorySize, smem);

    it_kernel<<<dim3(8, 6, Bn), 128>>>(x, Wi, bi);
    rnn_kernel<<<NCTA, 256, smem>>>(Wh, bh);
    final_kernel<<<dim3(6, Bn), 192>>>(Wf, bf, out);
}

// round 16
// speedup vs baseline: 1.0872x; 1.0872x over previous
#include <cuda_runtime.h>

#define Bn 256
#define Sn 336
#define Cn 321
#define Hn 512
#define Pn 96
#define NCTA 88
#define AROW 514   // As rows (512 + 2 prefetch pad)
#define BROW 514   // Bs rows (512 + 2 prefetch pad)

typedef unsigned long long ull;

__device__ float g_scr[(size_t)Bn * Cn * Hn];

__device__ __forceinline__ void fma2(ull &d, ull a, ull b) {
    asm("fma.rn.f32x2 %0, %1, %2, %0;" : "+l"(d) : "l"(a), "l"(b));
}
__device__ __forceinline__ ull dup2(float v) {
    ull r; asm("mov.b64 %0, {%1, %1};" : "=l"(r) : "f"(v)); return r;
}
__device__ __forceinline__ float2 up2(ull v) {
    float2 r; asm("mov.b64 {%0, %1}, %2;" : "=f"(r.x), "=f"(r.y) : "l"(v)); return r;
}
__device__ __forceinline__ float reluN(float x) { return (x < 0.f) ? 0.f : x; }
__device__ __forceinline__ void cluster_sync() {
    asm volatile("barrier.cluster.arrive.aligned;" ::: "memory");
    asm volatile("barrier.cluster.wait.aligned;" ::: "memory");
}

// ============================================================================
// it_kernel: IT[b,c,h] = bi[h] + sum_s x[b,s,c]*Wi[h,s]   (round-7, proven)
// ============================================================================
__global__ void __launch_bounds__(128) it_kernel(
    const float* __restrict__ x, const float* __restrict__ Wi,
    const float* __restrict__ bi)
{
    __shared__ __align__(16) float As[16][68];
    __shared__ __align__(16) float Bs[16][68];
    const int b  = blockIdx.z;
    const int n0 = blockIdx.x * 64;
    const int m0 = blockIdx.y * 64;
    const int t  = threadIdx.x;
    const int tm = t & 15, tn = t >> 4;

    ull acc[4][4];
#pragma unroll
    for (int i = 0; i < 4; i++)
#pragma unroll
        for (int j = 0; j < 4; j++) acc[i][j] = 0ull;

    const float* xb = x + (size_t)b * Sn * Cn;
    const int la_k = t >> 3, la_c = (t & 7) * 8;
    const int lb_n = t & 63, lb_k = (t >> 6) * 8;

    for (int k0 = 0; k0 < Sn; k0 += 16) {
        {
            const float* src = xb + (size_t)(k0 + la_k) * Cn + m0 + la_c;
#pragma unroll
            for (int j = 0; j < 8; j++)
                As[la_k][la_c + j] = (m0 + la_c + j < Cn) ? src[j] : 0.f;
        }
        {
            const float* src = Wi + (size_t)(n0 + lb_n) * Sn + k0 + lb_k;
            float4 v0 = *(const float4*)(src);
            float4 v1 = *(const float4*)(src + 4);
            Bs[lb_k + 0][lb_n] = v0.x; Bs[lb_k + 1][lb_n] = v0.y;
            Bs[lb_k + 2][lb_n] = v0.z; Bs[lb_k + 3][lb_n] = v0.w;
            Bs[lb_k + 4][lb_n] = v1.x; Bs[lb_k + 5][lb_n] = v1.y;
            Bs[lb_k + 6][lb_n] = v1.z; Bs[lb_k + 7][lb_n] = v1.w;
        }
        __syncthreads();
#pragma unroll
        for (int kk = 0; kk < 16; kk++) {
            float4 a = *(const float4*)&As[kk][tm * 4];
            const ull* bp = (const ull*)&Bs[kk][tn * 8];
            ull b0 = bp[0], b1 = bp[1], b2 = bp[2], b3 = bp[3];
            ull a0 = dup2(a.x), a1 = dup2(a.y), a2 = dup2(a.z), a3 = dup2(a.w);
            fma2(acc[0][0], a0, b0); fma2(acc[0][1], a0, b1);
            fma2(acc[0][2], a0, b2); fma2(acc[0][3], a0, b3);
            fma2(acc[1][0], a1, b0); fma2(acc[1][1], a1, b1);
            fma2(acc[1][2], a1, b2); fma2(acc[1][3], a1, b3);
            fma2(acc[2][0], a2, b0); fma2(acc[2][1], a2, b1);
            fma2(acc[2][2], a2, b2); fma2(acc[2][3], a2, b3);
            fma2(acc[3][0], a3, b0); fma2(acc[3][1], a3, b1);
            fma2(acc[3][2], a3, b2); fma2(acc[3][3], a3, b3);
        }
        __syncthreads();
    }
    float biv[8];
#pragma unroll
    for (int j = 0; j < 8; j++) biv[j] = bi[n0 + tn * 8 + j];
#pragma unroll
    for (int i = 0; i < 4; i++) {
        int c = m0 + tm * 4 + i;
        if (c < Cn) {
            float* dst = g_scr + ((size_t)b * Cn + c) * Hn + n0 + tn * 8;
#pragma unroll
            for (int j = 0; j < 4; j++) {
                float2 v = up2(acc[i][j]);
                dst[2 * j]     = v.x + biv[2 * j];
                dst[2 * j + 1] = v.y + biv[2 * j + 1];
            }
        }
    }
}

// ============================================================================
// Persistent recurrence (ONE launch, all 255 steps): 11 clusters x 8 CTAs,
// 256 threads.
//   Warps 0-3: consumers -- single uninterrupted 512-kk distance-2 register
//     pipeline (4c x 4n micro); fma2 order = k ascending 0..511, unchanged
//     -> bit-identical trajectory.
//   Warps 4-7: producers ONLY stage the full 512-k A tile (ping-pong LDG
//     batches), then park at cluster_sync. (Round-15 all-warp staging put
//     LDG latency on the consumer critical path: measured +2.5us/step.)
// Per step: 1 __syncthreads (post-stage) + 1 cluster_sync (post-epilogue).
// smem: Bs[514][64] + As[514][36] = 205.6KB, 1 CTA/SM.
// ============================================================================
extern __shared__ float sm_dyn[];

__global__ void __cluster_dims__(8, 1, 1) __launch_bounds__(256, 1) rnn_kernel(
    const float* __restrict__ Wh, const float* __restrict__ bh)
{
    float* Bs = sm_dyn;                     // Bs[k*64 + n], k < BROW
    float* As = sm_dyn + BROW * 64;         // As[kk*36 + c], kk < AROW

    const int t   = threadIdx.x;
    const int cta = blockIdx.x;
    const int n0  = (cta & 7) * 64;
    const int m0  = (cta >> 3) * 32;
    const bool consumer = (t < 128);
    const int tm  = t & 7;
    const int tn  = (t & 127) >> 3;

    // Wh^T resident: Bs[k][n] = Wh[n0+n][k]  (all 256 threads, 128 k each)
    {
        const int n = t & 63, kb = (t >> 6) * 128;
        const float* src = Wh + (size_t)(n0 + n) * Hn + kb;
        for (int k = 0; k < 128; k += 4) {
            float4 v = *(const float4*)(src + k);
            Bs[(kb + k + 0) * 64 + n] = v.x; Bs[(kb + k + 1) * 64 + n] = v.y;
            Bs[(kb + k + 2) * 64 + n] = v.z; Bs[(kb + k + 3) * 64 + n] = v.w;
        }
    }
    float bhv[4];
#pragma unroll
    for (int j = 0; j < 4; j++) bhv[j] = bh[n0 + tn * 4 + j];
    __syncthreads();

    // step 0: h0 = reluN(reluN(it+bh)+bh) on own tile (consumers)
    if (consumer) {
#pragma unroll
        for (int i = 0; i < 4; i++) {
            int c = m0 + tm * 4 + i;
            if (c < Cn) {
                float* row = g_scr + (size_t)c * Hn + n0 + tn * 4;
                float4 v = *(const float4*)row;
                float f[4] = { v.x, v.y, v.z, v.w };
#pragma unroll
                for (int j = 0; j < 4; j++) {
                    float a = reluN(f[j] + bhv[j]);
                    f[j] = reluN(a + bhv[j]);
                }
                *(float4*)row = make_float4(f[0], f[1], f[2], f[3]);
            }
        }
    }
    cluster_sync();

    // producer lane mapping: lane la_c owns c-row, warp w owns k-window
    // [w*128, w*128+128); stages in 4 ping-pong batches of 32 k.
    const int p     = t - 128;
    const int la_c  = p & 31;
    const int la_kw = (p >> 5) * 128;
    const bool cv   = consumer ? false : ((m0 + la_c) < Cn);

    for (int b = 1; b < Bn; b++) {
        float* itrow = g_scr + (size_t)b * (Cn * Hn);

        ull acc[4][2];
        float4 itv[4];

        if (consumer) {
#pragma unroll
            for (int i = 0; i < 4; i++) { acc[i][0] = 0ull; acc[i][1] = 0ull; }
#pragma unroll
            for (int i = 0; i < 4; i++) {
                int c = m0 + tm * 4 + i;
                itv[i] = (c < Cn)
                    ? *(const float4*)(itrow + (size_t)c * Hn + n0 + tn * 4)
                    : make_float4(0.f, 0.f, 0.f, 0.f);
            }
        } else {
            // stage full 512-k A tile: 4 batches of 8 float4, ping-pong
            const float* arow = g_scr + (size_t)(b - 1) * (Cn * Hn)
                              + (size_t)(m0 + la_c) * Hn + la_kw;
            float4 pA[8], pB[8];
#pragma unroll
            for (int q = 0; q < 8; q++)
                pA[q] = cv ? *(const float4*)(arow + q * 4)
                           : make_float4(0.f, 0.f, 0.f, 0.f);
#pragma unroll
            for (int batch = 0; batch < 4; batch++) {
                if (batch < 3) {
                    const float* s = arow + (batch + 1) * 32;
#pragma unroll
                    for (int q = 0; q < 8; q++)
                        pB[q] = cv ? *(const float4*)(s + q * 4)
                                   : make_float4(0.f, 0.f, 0.f, 0.f);
                }
                float* d = As;
#pragma unroll
                for (int q = 0; q < 8; q++) {
                    int kr = la_kw + batch * 32 + q * 4;
                    d[(kr + 0) * 36 + la_c] = pA[q].x;
                    d[(kr + 1) * 36 + la_c] = pA[q].y;
                    d[(kr + 2) * 36 + la_c] = pA[q].z;
                    d[(kr + 3) * 36 + la_c] = pA[q].w;
                }
#pragma unroll
                for (int q = 0; q < 8; q++) pA[q] = pB[q];
            }
        }
        __syncthreads();   // A tile fully staged

        if (consumer) {
            const float* as = As + tm * 4;
            const float* bs = Bs + tn * 4;

            // one uninterrupted 512-kk distance-2 register pipeline;
            // tail prefetches hit pad rows (never used in arithmetic).
            float4 aC = *(const float4*)(as);
            float4 aN = *(const float4*)(as + 36);
            ulonglong2 bC = *(const ulonglong2*)(bs);
            ulonglong2 bN = *(const ulonglong2*)(bs + 64);
#pragma unroll 1
            for (int kt = 0; kt < 32; kt++) {
                const float* asv = as + (kt * 16 + 2) * 36;
                const float* bsv = bs + (kt * 16 + 2) * 64;
#pragma unroll
                for (int kk = 0; kk < 16; kk++) {
                    float4 aP = *(const float4*)(asv + kk * 36);
                    ulonglong2 bP = *(const ulonglong2*)(bsv + kk * 64);
                    ull a0 = dup2(aC.x), a1 = dup2(aC.y),
                        a2 = dup2(aC.z), a3 = dup2(aC.w);
                    fma2(acc[0][0], a0, bC.x); fma2(acc[0][1], a0, bC.y);
                    fma2(acc[1][0], a1, bC.x); fma2(acc[1][1], a1, bC.y);
                    fma2(acc[2][0], a2, bC.x); fma2(acc[2][1], a2, bC.y);
                    fma2(acc[3][0], a3, bC.x); fma2(acc[3][1], a3, bC.y);
                    aC = aN; aN = aP;
                    bC = bN; bN = bP;
                }
            }

            // epilogue: h_b = reluN(reluN(it+hh)+hh), in place on g_scr[b]
#pragma unroll
            for (int i = 0; i < 4; i++) {
                int c = m0 + tm * 4 + i;
                if (c < Cn) {
                    float* row = itrow + (size_t)c * Hn + n0 + tn * 4;
                    float it[4] = { itv[i].x, itv[i].y, itv[i].z, itv[i].w };
                    float2 v0 = up2(acc[i][0]);
                    float2 v1 = up2(acc[i][1]);
                    float hh[4] = { v0.x + bhv[0], v0.y + bhv[1],
                                    v1.x + bhv[2], v1.y + bhv[3] };
                    float f[4];
#pragma unroll
                    for (int j = 0; j < 4; j++) {
                        float a = reluN(it[j] + hh[j]);
                        f[j] = reluN(a + hh[j]);
                    }
                    *(float4*)row = make_float4(f[0], f[1], f[2], f[3]);
                }
            }
        }
        // release next step's staging only after all epilogues in cluster;
        // also prevents overwriting As while consumers still read it.
        if (b < Bn - 1) cluster_sync();
    }
}

// ============================================================================
// final_kernel: tile 64c x 96p, micro 4c x 8p  (round-7, proven)
// ============================================================================
__global__ void __launch_bounds__(192) final_kernel(
    const float* __restrict__ Wf, const float* __restrict__ bf,
    float* __restrict__ out)
{
    __shared__ __align__(16) float As[16][68];
    __shared__ __align__(16) float Bs[16][100];
    const int b  = blockIdx.y;
    const int m0 = blockIdx.x * 64;
    const int t  = threadIdx.x;
    const int tm = t & 15;
    const int tn = t >> 4;

    ull acc[4][4];
#pragma unroll
    for (int i = 0; i < 4; i++)
#pragma unroll
        for (int j = 0; j < 4; j++) acc[i][j] = 0ull;

    const float* hb = g_scr + (size_t)b * Cn * Hn;
    const int la_c = t >> 1, la_k = (t & 1) * 8;
    const int lb_p = t % 96,  lb_k = (t / 96) * 8;

    for (int k0 = 0; k0 < Hn; k0 += 16) {
        if (t < 128) {
            int c = m0 + la_c;
            if (c < Cn) {
                const float* src = hb + (size_t)c * Hn + k0 + la_k;
                float4 v0 = *(const float4*)(src);
                float4 v1 = *(const float4*)(src + 4);
                As[la_k + 0][la_c] = v0.x; As[la_k + 1][la_c] = v0.y;
                As[la_k + 2][la_c] = v0.z; As[la_k + 3][la_c] = v0.w;
                As[la_k + 4][la_c] = v1.x; As[la_k + 5][la_c] = v1.y;
                As[la_k + 6][la_c] = v1.z; As[la_k + 7][la_c] = v1.w;
            } else {
#pragma unroll
                for (int j = 0; j < 8; j++) As[la_k + j][la_c] = 0.f;
            }
        }
        {
            const float* src = Wf + (size_t)lb_p * Hn + k0 + lb_k;
            float4 v0 = *(const float4*)(src);
            float4 v1 = *(const float4*)(src + 4);
            Bs[lb_k + 0][lb_p] = v0.x; Bs[lb_k + 1][lb_p] = v0.y;
            Bs[lb_k + 2][lb_p] = v0.z; Bs[lb_k + 3][lb_p] = v0.w;
            Bs[lb_k + 4][lb_p] = v1.x; Bs[lb_k + 5][lb_p] = v1.y;
            Bs[lb_k + 6][lb_p] = v1.z; Bs[lb_k + 7][lb_p] = v1.w;
        }
        __syncthreads();
#pragma unroll
        for (int kk = 0; kk < 16; kk++) {
            float4 a = *(const float4*)&As[kk][tm * 4];
            ulonglong2 b01 = *(const ulonglong2*)&Bs[kk][tn * 8];
            ulonglong2 b23 = *(const ulonglong2*)&Bs[kk][tn * 8 + 4];
            ull a0 = dup2(a.x), a1 = dup2(a.y), a2 = dup2(a.z), a3 = dup2(a.w);
            fma2(acc[0][0], a0, b01.x); fma2(acc[0][1], a0, b01.y);
            fma2(acc[0][2], a0, b23.x); fma2(acc[0][3], a0, b23.y);
            fma2(acc[1][0], a1, b01.x); fma2(acc[1][1], a1, b01.y);
            fma2(acc[1][2], a1, b23.x); fma2(acc[1][3], a1, b23.y);
            fma2(acc[2][0], a2, b01.x); fma2(acc[2][1], a2, b01.y);
            fma2(acc[2][2], a2, b23.x); fma2(acc[2][3], a2, b23.y);
            fma2(acc[3][0], a3, b01.x); fma2(acc[3][1], a3, b01.y);
            fma2(acc[3][2], a3, b23.x); fma2(acc[3][3], a3, b23.y);
        }
        __syncthreads();
    }
    float bfv[8];
#pragma unroll
    for (int j = 0; j < 8; j++) bfv[j] = bf[tn * 8 + j];
#pragma unroll
    for (int i = 0; i < 4; i++) {
        int c = m0 + tm * 4 + i;
        if (c < Cn) {
            size_t base = ((size_t)b * Pn + tn * 8) * Cn + c;
#pragma unroll
            for (int j = 0; j < 4; j++) {
                float2 v = up2(acc[i][j]);
                float z0 = v.x + bfv[2 * j];
                float z1 = v.y + bfv[2 * j + 1];
                out[base + (size_t)(2 * j) * Cn]     = (z0 >= 0.f) ? 1.f : 0.f;
                out[base + (size_t)(2 * j + 1) * Cn] = (z1 >= 0.f) ? 1.f : 0.f;
            }
        }
    }
}

// ============================================================================
extern "C" void kernel_launch(void* const* d_in, const int* in_sizes, int n_in,
                              void* d_out, int out_size) {
    const float* x  = (const float*)d_in[0];
    const float* Wi = (const float*)d_in[1];
    const float* bi = (const float*)d_in[2];
    const float* Wh = (const float*)d_in[3];
    const float* bh = (const float*)d_in[4];
    const float* Wf = (const float*)d_in[5];
    const float* bf = (const float*)d_in[6];
    float* out = (float*)d_out;

    const int smem = (BROW * 64 + AROW * 36) * 4;  // 205600 B
    cudaFuncSetAttribute(rnn_kernel,
                         cudaFuncAttributeMaxDynamicSharedMemorySize, smem);

    it_kernel<<<dim3(8, 6, Bn), 128>>>(x, Wi, bi);
    rnn_kernel<<<NCTA, 256, smem>>>(Wh, bh);
    final_kernel<<<dim3(6, Bn), 192>>>(Wf, bf, out);
}

// round 17
// speedup vs baseline: 1.1035x; 1.0150x over previous
#include <cuda_runtime.h>

#define Bn 256
#define Sn 336
#define Cn 321
#define Hn 512
#define Pn 96
#define NCTA 88
#define AROW 514   // As rows (512 + 2 prefetch pad)
#define BROW 514   // Bs rows (512 + 2 prefetch pad)

typedef unsigned long long ull;

__device__ float g_scr[(size_t)Bn * Cn * Hn];

__device__ __forceinline__ void fma2(ull &d, ull a, ull b) {
    asm("fma.rn.f32x2 %0, %1, %2, %0;" : "+l"(d) : "l"(a), "l"(b));
}
__device__ __forceinline__ ull dup2(float v) {
    ull r; asm("mov.b64 %0, {%1, %1};" : "=l"(r) : "f"(v)); return r;
}
__device__ __forceinline__ float2 up2(ull v) {
    float2 r; asm("mov.b64 {%0, %1}, %2;" : "=f"(r.x), "=f"(r.y) : "l"(v)); return r;
}
__device__ __forceinline__ float reluN(float x) { return (x < 0.f) ? 0.f : x; }
__device__ __forceinline__ void cluster_sync() {
    asm volatile("barrier.cluster.arrive.aligned;" ::: "memory");
    asm volatile("barrier.cluster.wait.aligned;" ::: "memory");
}

// ============================================================================
// it_kernel v2: IT[b,c,h] = bi[h] + sum_s x[b,s,c]*Wi[h,s]
// Tile 64c x 128h, 128 threads, micro 8c x 8h (fma-pipe-dominated; ~25% less
// smem traffic per MAC than 4c x 8h). Per-output k chain ascending, bias at
// end -> bit-identical IT vs previous version.
// ============================================================================
__global__ void __launch_bounds__(128) it_kernel(
    const float* __restrict__ x, const float* __restrict__ Wi,
    const float* __restrict__ bi)
{
    __shared__ __align__(16) float As[16][68];    // [kk][c]
    __shared__ __align__(16) float Bs[16][132];   // [kk][h]
    const int b  = blockIdx.z;
    const int n0 = blockIdx.x * 128;
    const int m0 = blockIdx.y * 64;
    const int t  = threadIdx.x;
    const int tm = t & 7;      // 8 c-groups of 8c
    const int tn = t >> 3;     // 16 h-groups of 8h

    ull acc[8][4];
#pragma unroll
    for (int i = 0; i < 8; i++)
#pragma unroll
        for (int j = 0; j < 4; j++) acc[i][j] = 0ull;

    const float* xb = x + (size_t)b * Sn * Cn;
    const int la_k = t >> 3, la_c = (t & 7) * 8;

    for (int k0 = 0; k0 < Sn; k0 += 16) {
        // A: x[b][k0+la_k][m0+la_c .. +8)  (c-contiguous, coalesced)
        {
            const float* src = xb + (size_t)(k0 + la_k) * Cn + m0 + la_c;
#pragma unroll
            for (int j = 0; j < 8; j++)
                As[la_k][la_c + j] = (m0 + la_c + j < Cn) ? src[j] : 0.f;
        }
        // B: Wi[n0+t][k0 .. +16) -> Bs[kk][t]
        {
            const float* src = Wi + (size_t)(n0 + t) * Sn + k0;
#pragma unroll
            for (int g = 0; g < 4; g++) {
                float4 v = *(const float4*)(src + g * 4);
                Bs[g * 4 + 0][t] = v.x; Bs[g * 4 + 1][t] = v.y;
                Bs[g * 4 + 2][t] = v.z; Bs[g * 4 + 3][t] = v.w;
            }
        }
        __syncthreads();
#pragma unroll
        for (int kk = 0; kk < 16; kk++) {
            float4 a0 = *(const float4*)&As[kk][tm * 8];
            float4 a1 = *(const float4*)&As[kk][tm * 8 + 4];
            ulonglong2 b01 = *(const ulonglong2*)&Bs[kk][tn * 8];
            ulonglong2 b23 = *(const ulonglong2*)&Bs[kk][tn * 8 + 4];
            ull d[8] = { dup2(a0.x), dup2(a0.y), dup2(a0.z), dup2(a0.w),
                         dup2(a1.x), dup2(a1.y), dup2(a1.z), dup2(a1.w) };
#pragma unroll
            for (int i = 0; i < 8; i++) {
                fma2(acc[i][0], d[i], b01.x);
                fma2(acc[i][1], d[i], b01.y);
                fma2(acc[i][2], d[i], b23.x);
                fma2(acc[i][3], d[i], b23.y);
            }
        }
        __syncthreads();
    }
    float biv[8];
#pragma unroll
    for (int j = 0; j < 8; j++) biv[j] = bi[n0 + tn * 8 + j];
#pragma unroll
    for (int i = 0; i < 8; i++) {
        int c = m0 + tm * 8 + i;
        if (c < Cn) {
            float* dst = g_scr + ((size_t)b * Cn + c) * Hn + n0 + tn * 8;
#pragma unroll
            for (int j = 0; j < 4; j++) {
                float2 v = up2(acc[i][j]);
                dst[2 * j]     = v.x + biv[2 * j];
                dst[2 * j + 1] = v.y + biv[2 * j + 1];
            }
        }
    }
}

// ============================================================================
// Persistent recurrence (one launch): 11 clusters x 8 CTAs, 256 threads.
//   Warps 0-3: consumers -- 512-kk distance-2 register pipeline, SPLIT into
//     two 256-k windows (accumulators carry; fma2 order = k ascending 0..511
//     unchanged -> bit-identical trajectory).
//   Warps 4-7: producers -- stage window0, then stage window1 WHILE consumers
//     compute window0 (overlaps ~half the staging; producer LDG/STS also
//     covers consumer stalls during compute).
// Per step: 2 __syncthreads + 1 cluster_sync.
// smem: Bs[514][64] + As[514][36] = 205.6KB, 1 CTA/SM.
// ============================================================================
extern __shared__ float sm_dyn[];

__global__ void __cluster_dims__(8, 1, 1) __launch_bounds__(256, 1) rnn_kernel(
    const float* __restrict__ Wh, const float* __restrict__ bh)
{
    float* Bs = sm_dyn;                     // Bs[k*64 + n], k < BROW
    float* As = sm_dyn + BROW * 64;         // As[kk*36 + c], kk < AROW

    const int t   = threadIdx.x;
    const int cta = blockIdx.x;
    const int n0  = (cta & 7) * 64;
    const int m0  = (cta >> 3) * 32;
    const bool consumer = (t < 128);
    const int tm  = t & 7;
    const int tn  = (t & 127) >> 3;

    // Wh^T resident: Bs[k][n] = Wh[n0+n][k]  (all 256 threads, 128 k each)
    {
        const int n = t & 63, kb = (t >> 6) * 128;
        const float* src = Wh + (size_t)(n0 + n) * Hn + kb;
        for (int k = 0; k < 128; k += 4) {
            float4 v = *(const float4*)(src + k);
            Bs[(kb + k + 0) * 64 + n] = v.x; Bs[(kb + k + 1) * 64 + n] = v.y;
            Bs[(kb + k + 2) * 64 + n] = v.z; Bs[(kb + k + 3) * 64 + n] = v.w;
        }
    }
    float bhv[4];
#pragma unroll
    for (int j = 0; j < 4; j++) bhv[j] = bh[n0 + tn * 4 + j];
    __syncthreads();

    // step 0: h0 = reluN(reluN(it+bh)+bh) on own tile (consumers)
    if (consumer) {
#pragma unroll
        for (int i = 0; i < 4; i++) {
            int c = m0 + tm * 4 + i;
            if (c < Cn) {
                float* row = g_scr + (size_t)c * Hn + n0 + tn * 4;
                float4 v = *(const float4*)row;
                float f[4] = { v.x, v.y, v.z, v.w };
#pragma unroll
                for (int j = 0; j < 4; j++) {
                    float a = reluN(f[j] + bhv[j]);
                    f[j] = reluN(a + bhv[j]);
                }
                *(float4*)row = make_float4(f[0], f[1], f[2], f[3]);
            }
        }
    }
    cluster_sync();

    // producer lane mapping: lane la_c owns c-row; producer warp pw (0..3)
    // owns k-subwindow [w*256 + pw*64, +64) of staging window w (0/1).
    const int p     = t - 128;
    const int la_c  = p & 31;
    const int la_pw = (p >> 5) * 64;
    const bool cv   = consumer ? false : ((m0 + la_c) < Cn);

    for (int b = 1; b < Bn; b++) {
        float* itrow = g_scr + (size_t)b * (Cn * Hn);
        const float* arow = consumer ? 0
            : g_scr + (size_t)(b - 1) * (Cn * Hn) + (size_t)(m0 + la_c) * Hn;

        ull acc[4][2];
        float4 itv[4];

        if (consumer) {
#pragma unroll
            for (int i = 0; i < 4; i++) { acc[i][0] = 0ull; acc[i][1] = 0ull; }
#pragma unroll
            for (int i = 0; i < 4; i++) {
                int c = m0 + tm * 4 + i;
                itv[i] = (c < Cn)
                    ? *(const float4*)(itrow + (size_t)c * Hn + n0 + tn * 4)
                    : make_float4(0.f, 0.f, 0.f, 0.f);
            }
        } else {
            // stage window 0: k in [la_pw, la_pw+64)
            const float* s = arow + la_pw;
            float4 pre[16];
#pragma unroll
            for (int q = 0; q < 16; q++)
                pre[q] = cv ? *(const float4*)(s + q * 4)
                            : make_float4(0.f, 0.f, 0.f, 0.f);
#pragma unroll
            for (int q = 0; q < 16; q++) {
                int kr = la_pw + q * 4;
                As[(kr + 0) * 36 + la_c] = pre[q].x;
                As[(kr + 1) * 36 + la_c] = pre[q].y;
                As[(kr + 2) * 36 + la_c] = pre[q].z;
                As[(kr + 3) * 36 + la_c] = pre[q].w;
            }
        }
        __syncthreads();   // window 0 staged

        if (consumer) {
            // compute window 0: k 0..255 (distance-2 pipeline; tail prefetch
            // touches rows 256/257 concurrently staged -- values discarded)
            const float* as = As + tm * 4;
            const float* bs = Bs + tn * 4;
            float4 aC = *(const float4*)(as);
            float4 aN = *(const float4*)(as + 36);
            ulonglong2 bC = *(const ulonglong2*)(bs);
            ulonglong2 bN = *(const ulonglong2*)(bs + 64);
#pragma unroll 1
            for (int kt = 0; kt < 16; kt++) {
                const float* asv = as + (kt * 16 + 2) * 36;
                const float* bsv = bs + (kt * 16 + 2) * 64;
#pragma unroll
                for (int kk = 0; kk < 16; kk++) {
                    float4 aP = *(const float4*)(asv + kk * 36);
                    ulonglong2 bP = *(const ulonglong2*)(bsv + kk * 64);
                    ull a0 = dup2(aC.x), a1 = dup2(aC.y),
                        a2 = dup2(aC.z), a3 = dup2(aC.w);
                    fma2(acc[0][0], a0, bC.x); fma2(acc[0][1], a0, bC.y);
                    fma2(acc[1][0], a1, bC.x); fma2(acc[1][1], a1, bC.y);
                    fma2(acc[2][0], a2, bC.x); fma2(acc[2][1], a2, bC.y);
                    fma2(acc[3][0], a3, bC.x); fma2(acc[3][1], a3, bC.y);
                    aC = aN; aN = aP;
                    bC = bN; bN = bP;
                }
            }
        } else {
            // stage window 1: k in [256 + la_pw, 256 + la_pw + 64)
            const float* s = arow + 256 + la_pw;
            float4 pre[16];
#pragma unroll
            for (int q = 0; q < 16; q++)
                pre[q] = cv ? *(const float4*)(s + q * 4)
                            : make_float4(0.f, 0.f, 0.f, 0.f);
#pragma unroll
            for (int q = 0; q < 16; q++) {
                int kr = 256 + la_pw + q * 4;
                As[(kr + 0) * 36 + la_c] = pre[q].x;
                As[(kr + 1) * 36 + la_c] = pre[q].y;
                As[(kr + 2) * 36 + la_c] = pre[q].z;
                As[(kr + 3) * 36 + la_c] = pre[q].w;
            }
        }
        __syncthreads();   // window 1 staged, window 0 consumed

        if (consumer) {
            // compute window 1: k 256..511 (re-init pipeline from staged
            // rows; tail prefetch hits pad rows 512/513, never used)
            const float* as = As + 256 * 36 + tm * 4;
            const float* bs = Bs + 256 * 64 + tn * 4;
            float4 aC = *(const float4*)(as);
            float4 aN = *(const float4*)(as + 36);
            ulonglong2 bC = *(const ulonglong2*)(bs);
            ulonglong2 bN = *(const ulonglong2*)(bs + 64);
#pragma unroll 1
            for (int kt = 0; kt < 16; kt++) {
                const float* asv = as + (kt * 16 + 2) * 36;
                const float* bsv = bs + (kt * 16 + 2) * 64;
#pragma unroll
                for (int kk = 0; kk < 16; kk++) {
                    float4 aP = *(const float4*)(asv + kk * 36);
                    ulonglong2 bP = *(const ulonglong2*)(bsv + kk * 64);
                    ull a0 = dup2(aC.x), a1 = dup2(aC.y),
                        a2 = dup2(aC.z), a3 = dup2(aC.w);
                    fma2(acc[0][0], a0, bC.x); fma2(acc[0][1], a0, bC.y);
                    fma2(acc[1][0], a1, bC.x); fma2(acc[1][1], a1, bC.y);
                    fma2(acc[2][0], a2, bC.x); fma2(acc[2][1], a2, bC.y);
                    fma2(acc[3][0], a3, bC.x); fma2(acc[3][1], a3, bC.y);
                    aC = aN; aN = aP;
                    bC = bN; bN = bP;
                }
            }

            // epilogue: h_b = reluN(reluN(it+hh)+hh), in place on g_scr[b]
#pragma unroll
            for (int i = 0; i < 4; i++) {
                int c = m0 + tm * 4 + i;
                if (c < Cn) {
                    float* row = itrow + (size_t)c * Hn + n0 + tn * 4;
                    float it[4] = { itv[i].x, itv[i].y, itv[i].z, itv[i].w };
                    float2 v0 = up2(acc[i][0]);
                    float2 v1 = up2(acc[i][1]);
                    float hh[4] = { v0.x + bhv[0], v0.y + bhv[1],
                                    v1.x + bhv[2], v1.y + bhv[3] };
                    float f[4];
#pragma unroll
                    for (int j = 0; j < 4; j++) {
                        float a = reluN(it[j] + hh[j]);
                        f[j] = reluN(a + hh[j]);
                    }
                    *(float4*)row = make_float4(f[0], f[1], f[2], f[3]);
                }
            }
        }
        if (b < Bn - 1) cluster_sync();
    }
}

// ============================================================================
// final_kernel: tile 64c x 96p, micro 4c x 8p  (round-7, proven)
// ============================================================================
__global__ void __launch_bounds__(192) final_kernel(
    const float* __restrict__ Wf, const float* __restrict__ bf,
    float* __restrict__ out)
{
    __shared__ __align__(16) float As[16][68];
    __shared__ __align__(16) float Bs[16][100];
    const int b  = blockIdx.y;
    const int m0 = blockIdx.x * 64;
    const int t  = threadIdx.x;
    const int tm = t & 15;
    const int tn = t >> 4;

    ull acc[4][4];
#pragma unroll
    for (int i = 0; i < 4; i++)
#pragma unroll
        for (int j = 0; j < 4; j++) acc[i][j] = 0ull;

    const float* hb = g_scr + (size_t)b * Cn * Hn;
    const int la_c = t >> 1, la_k = (t & 1) * 8;
    const int lb_p = t % 96,  lb_k = (t / 96) * 8;

    for (int k0 = 0; k0 < Hn; k0 += 16) {
        if (t < 128) {
            int c = m0 + la_c;
            if (c < Cn) {
                const float* src = hb + (size_t)c * Hn + k0 + la_k;
                float4 v0 = *(const float4*)(src);
                float4 v1 = *(const float4*)(src + 4);
                As[la_k + 0][la_c] = v0.x; As[la_k + 1][la_c] = v0.y;
                As[la_k + 2][la_c] = v0.z; As[la_k + 3][la_c] = v0.w;
                As[la_k + 4][la_c] = v1.x; As[la_k + 5][la_c] = v1.y;
                As[la_k + 6][la_c] = v1.z; As[la_k + 7][la_c] = v1.w;
            } else {
#pragma unroll
                for (int j = 0; j < 8; j++) As[la_k + j][la_c] = 0.f;
            }
        }
        {
            const float* src = Wf + (size_t)lb_p * Hn + k0 + lb_k;
            float4 v0 = *(const float4*)(src);
            float4 v1 = *(const float4*)(src + 4);
            Bs[lb_k + 0][lb_p] = v0.x; Bs[lb_k + 1][lb_p] = v0.y;
            Bs[lb_k + 2][lb_p] = v0.z; Bs[lb_k + 3][lb_p] = v0.w;
            Bs[lb_k + 4][lb_p] = v1.x; Bs[lb_k + 5][lb_p] = v1.y;
            Bs[lb_k + 6][lb_p] = v1.z; Bs[lb_k + 7][lb_p] = v1.w;
        }
        __syncthreads();
#pragma unroll
        for (int kk = 0; kk < 16; kk++) {
            float4 a = *(const float4*)&As[kk][tm * 4];
            ulonglong2 b01 = *(const ulonglong2*)&Bs[kk][tn * 8];
            ulonglong2 b23 = *(const ulonglong2*)&Bs[kk][tn * 8 + 4];
            ull a0 = dup2(a.x), a1 = dup2(a.y), a2 = dup2(a.z), a3 = dup2(a.w);
            fma2(acc[0][0], a0, b01.x); fma2(acc[0][1], a0, b01.y);
            fma2(acc[0][2], a0, b23.x); fma2(acc[0][3], a0, b23.y);
            fma2(acc[1][0], a1, b01.x); fma2(acc[1][1], a1, b01.y);
            fma2(acc[1][2], a1, b23.x); fma2(acc[1][3], a1, b23.y);
            fma2(acc[2][0], a2, b01.x); fma2(acc[2][1], a2, b01.y);
            fma2(acc[2][2], a2, b23.x); fma2(acc[2][3], a2, b23.y);
            fma2(acc[3][0], a3, b01.x); fma2(acc[3][1], a3, b01.y);
            fma2(acc[3][2], a3, b23.x); fma2(acc[3][3], a3, b23.y);
        }
        __syncthreads();
    }
    float bfv[8];
#pragma unroll
    for (int j = 0; j < 8; j++) bfv[j] = bf[tn * 8 + j];
#pragma unroll
    for (int i = 0; i < 4; i++) {
        int c = m0 + tm * 4 + i;
        if (c < Cn) {
            size_t base = ((size_t)b * Pn + tn * 8) * Cn + c;
#pragma unroll
            for (int j = 0; j < 4; j++) {
                float2 v = up2(acc[i][j]);
                float z0 = v.x + bfv[2 * j];
                float z1 = v.y + bfv[2 * j + 1];
                out[base + (size_t)(2 * j) * Cn]     = (z0 >= 0.f) ? 1.f : 0.f;
                out[base + (size_t)(2 * j + 1) * Cn] = (z1 >= 0.f) ? 1.f : 0.f;
            }
        }
    }
}

// ============================================================================
extern "C" void kernel_launch(void* const* d_in, const int* in_sizes, int n_in,
                              void* d_out, int out_size) {
    const float* x  = (const float*)d_in[0];
    const float* Wi = (const float*)d_in[1];
    const float* bi = (const float*)d_in[2];
    const float* Wh = (const float*)d_in[3];
    const float* bh = (const float*)d_in[4];
    const float* Wf = (const float*)d_in[5];
    const float* bf = (const float*)d_in[6];
    float* out = (float*)d_out;

    const int smem = (BROW * 64 + AROW * 36) * 4;  // 205600 B
    cudaFuncSetAttribute(rnn_kernel,
                         cudaFuncAttributeMaxDynamicSharedMemorySize, smem);

    it_kernel<<<dim3(4, 6, Bn), 128>>>(x, Wi, bi);
    rnn_kernel<<<NCTA, 256, smem>>>(Wh, bh);
    final_kernel<<<dim3(6, Bn), 192>>>(Wf, bf, out);
}